// round 4
// baseline (speedup 1.0000x reference)
#include <cuda_runtime.h>

#define BB 1024
#define TT 512
#define IN_DIM 16
#define HH 64
#define G3 192

// Scratch (device globals — allocation-free per harness rules)
__device__ float g_gx[(size_t)TT * BB * G3];   // [t][b][192]  (384 MiB)
__device__ float g_out[(size_t)TT * BB * HH];  // [t][b][64]   (128 MiB)

__device__ __forceinline__ float fsigmoid(float x) {
    // 1/(1+e^-x); robust at extremes: exp->inf => 0, exp->0 => 1
    return __fdividef(1.0f, 1.0f + __expf(-x));
}
__device__ __forceinline__ float ftanhf(float x) {
    // 1 - 2/(e^{2x}+1); x->+inf: e=inf => 1; x->-inf: e=0 => -1
    float e = __expf(2.0f * x);
    return 1.0f - __fdividef(2.0f, e + 1.0f);
}

// ---------------------------------------------------------------------------
// gx GEMM: g_gx[t][b][g] = bias[g] + sum_k in[b,t,k] * W[g,k]
// Block: 64 rows (fixed t, 64 consecutive b) x all 192 gates, 256 threads,
// thread tile 8 rows x 6 gates. Grid (16, 512).
// ---------------------------------------------------------------------------
template <int K>
__global__ void __launch_bounds__(256) gx_gemm(
    const float* __restrict__ in, long sb, long st,
    const float* __restrict__ W, const float* __restrict__ bias)
{
    extern __shared__ float sm[];
    float* ws  = sm;            // [K][192]
    float* ins = sm + K * G3;   // [K][64]

    const int t   = blockIdx.y;
    const int b0  = blockIdx.x * 64;
    const int tid = threadIdx.x;

    for (int e = tid; e < G3 * K; e += 256) {
        int g = e / K, k = e % K;
        ws[k * G3 + g] = W[e];
    }
    for (int e = tid; e < 64 * K; e += 256) {
        int m = e / K, k = e % K;
        ins[k * 64 + m] = in[(size_t)(b0 + m) * sb + (size_t)t * st + k];
    }
    __syncthreads();

    const int lane = tid & 31;
    const int mg   = tid >> 5;
    const int g0   = lane * 6;
    const int m0   = mg * 8;

    float acc[8][6];
#pragma unroll
    for (int i = 0; i < 8; i++)
#pragma unroll
        for (int j = 0; j < 6; j++) acc[i][j] = 0.0f;

#pragma unroll
    for (int k = 0; k < K; ++k) {
        const float* ik = ins + k * 64 + m0;
        float4 a0 = *(const float4*)(ik);
        float4 a1 = *(const float4*)(ik + 4);
        const float* wk = ws + k * G3 + g0;
        float2 w0 = *(const float2*)(wk);
        float2 w1 = *(const float2*)(wk + 2);
        float2 w2 = *(const float2*)(wk + 4);
        float av[8] = {a0.x, a0.y, a0.z, a0.w, a1.x, a1.y, a1.z, a1.w};
        float wv[6] = {w0.x, w0.y, w1.x, w1.y, w2.x, w2.y};
#pragma unroll
        for (int i = 0; i < 8; i++)
#pragma unroll
            for (int j = 0; j < 6; j++)
                acc[i][j] = fmaf(av[i], wv[j], acc[i][j]);
    }

    float bb[6];
#pragma unroll
    for (int j = 0; j < 6; j++) bb[j] = __ldg(bias + g0 + j);

#pragma unroll
    for (int i = 0; i < 8; i++) {
        float* op = g_gx + ((size_t)t * BB + b0 + m0 + i) * G3 + g0;
        float2 v;
        v.x = acc[i][0] + bb[0]; v.y = acc[i][1] + bb[1]; *(float2*)(op)     = v;
        v.x = acc[i][2] + bb[2]; v.y = acc[i][3] + bb[3]; *(float2*)(op + 2) = v;
        v.x = acc[i][4] + bb[4]; v.y = acc[i][5] + bb[5]; *(float2*)(op + 4) = v;
    }
}

// ---------------------------------------------------------------------------
// Recurrent GRU layer: reads g_gx, writes g_out. 128 blocks x 256 threads.
// One warp == one batch row: no block barriers in the t-loop.
// Shared: W_hh paired as wp[k2][192][2] (48KB, conflict-free LDS.128),
//         hsh[8][64] (h state), ghs[8][192] (gate exchange).
// ---------------------------------------------------------------------------
__global__ void __launch_bounds__(256, 1) gru_rec(
    const float* __restrict__ Whh, const float* __restrict__ bhh)
{
    extern __shared__ float sm[];
    float* wp  = sm;               // 12288 floats
    float* hsh = sm + 12288;       // 512
    float* ghs = sm + 12800;       // 1536

    const int tid  = threadIdx.x;
    const int w    = tid >> 5;
    const int lane = tid & 31;
    const int b    = blockIdx.x * 8 + w;
    const int g0   = lane * 6;

    // wp[k2][g][c] = Whh[g*64 + 2*k2 + c]
    for (int e = tid; e < G3 * HH; e += 256) {
        int g = e >> 6, k = e & 63;
        wp[((size_t)(k >> 1) * G3 + g) * 2 + (k & 1)] = Whh[e];
    }
    for (int e = tid; e < 8 * HH; e += 256) hsh[e] = 0.0f;

    float bh[6];
#pragma unroll
    for (int j = 0; j < 6; j++) bh[j] = __ldg(bhh + g0 + j);
    __syncthreads();

    float* hrow = hsh + w * HH;
    float* grow = ghs + w * G3;
    const float* gbase = g_gx + (size_t)b * G3 + lane;
    float* obase = g_out + (size_t)b * HH + lane;
    const float4* wq = (const float4*)(wp + (size_t)g0 * 2);  // 48B/lane, 16B-aligned

    float h0 = 0.0f, h1 = 0.0f;

    // prefetch gx for t=0 (update-thread pattern: j = lane + {0,32,...,160})
    float nx[6];
#pragma unroll
    for (int j = 0; j < 6; j++) nx[j] = __ldg(gbase + j * 32);

#pragma unroll 1
    for (int t = 0; t < TT; ++t) {
        float cx[6];
#pragma unroll
        for (int j = 0; j < 6; j++) cx[j] = nx[j];
        // prefetch next timestep's gx (clamped at the end; values unused)
        const float* gnext = gbase + (size_t)((t + 1 < TT) ? t + 1 : t) * (BB * G3);
#pragma unroll
        for (int j = 0; j < 6; j++) nx[j] = __ldg(gnext + j * 32);

        // --- dot phase: gh[g0..g0+5] = b_hh + W_hh . h ---
        float a0 = bh[0], a1 = bh[1], a2 = bh[2], a3 = bh[3], a4 = bh[4], a5 = bh[5];
#pragma unroll
        for (int k2 = 0; k2 < 32; ++k2) {
            float2 hh = *(const float2*)(hrow + k2 * 2);   // broadcast
            float4 q0 = wq[k2 * 96 + 0];
            float4 q1 = wq[k2 * 96 + 1];
            float4 q2 = wq[k2 * 96 + 2];
            a0 = fmaf(q0.x, hh.x, a0); a0 = fmaf(q0.y, hh.y, a0);
            a1 = fmaf(q0.z, hh.x, a1); a1 = fmaf(q0.w, hh.y, a1);
            a2 = fmaf(q1.x, hh.x, a2); a2 = fmaf(q1.y, hh.y, a2);
            a3 = fmaf(q1.z, hh.x, a3); a3 = fmaf(q1.w, hh.y, a3);
            a4 = fmaf(q2.x, hh.x, a4); a4 = fmaf(q2.y, hh.y, a4);
            a5 = fmaf(q2.z, hh.x, a5); a5 = fmaf(q2.w, hh.y, a5);
        }
        *(float2*)(grow + g0)     = make_float2(a0, a1);
        *(float2*)(grow + g0 + 2) = make_float2(a2, a3);
        *(float2*)(grow + g0 + 4) = make_float2(a4, a5);
        __syncwarp();

        // --- update phase: this lane owns h[lane] and h[lane+32] ---
        float hr0 = grow[lane],       hr1 = grow[lane + 32];
        float hz0 = grow[lane + 64],  hz1 = grow[lane + 96];
        float hn0 = grow[lane + 128], hn1 = grow[lane + 160];

        float r0 = fsigmoid(cx[0] + hr0), r1 = fsigmoid(cx[1] + hr1);
        float z0 = fsigmoid(cx[2] + hz0), z1 = fsigmoid(cx[3] + hz1);
        float n0 = ftanhf(fmaf(r0, hn0, cx[4]));
        float n1 = ftanhf(fmaf(r1, hn1, cx[5]));
        h0 = fmaf(z0, h0 - n0, n0);   // (1-z)*n + z*h
        h1 = fmaf(z1, h1 - n1, n1);

        hrow[lane]      = h0;
        hrow[lane + 32] = h1;
        obase[(size_t)t * (BB * HH)]      = h0;
        obase[(size_t)t * (BB * HH) + 32] = h1;
        __syncwarp();
    }
}

// ---------------------------------------------------------------------------
// Head: y[b] = fc2_b + fc2_w . relu(fc1_w @ h_last[b] + fc1_b)
// ---------------------------------------------------------------------------
__global__ void __launch_bounds__(256) head_kernel(
    const float* __restrict__ fc1w, const float* __restrict__ fc1b,
    const float* __restrict__ fc2w, const float* __restrict__ fc2b,
    float* __restrict__ y)
{
    __shared__ float s1[32 * 64];
    __shared__ float sb1[32];
    __shared__ float sw2[32];
    const int tid = threadIdx.x;
    for (int e = tid; e < 2048; e += 256) s1[e] = fc1w[e];
    if (tid < 32) { sb1[tid] = fc1b[tid]; sw2[tid] = fc2w[tid]; }
    __syncthreads();

    const int b = blockIdx.x * 256 + tid;
    const float* hp = g_out + (size_t)(TT - 1) * BB * HH + (size_t)b * HH;
    float hv[64];
#pragma unroll
    for (int q = 0; q < 16; q++) {
        float4 v = *(const float4*)(hp + q * 4);
        hv[q * 4] = v.x; hv[q * 4 + 1] = v.y; hv[q * 4 + 2] = v.z; hv[q * 4 + 3] = v.w;
    }
    float acc = __ldg(fc2b);
#pragma unroll
    for (int j = 0; j < 32; j++) {
        float s = sb1[j];
#pragma unroll
        for (int k = 0; k < 64; k++) s = fmaf(s1[j * 64 + k], hv[k], s);
        acc = fmaf(sw2[j], fmaxf(s, 0.0f), acc);
    }
    y[b] = acc;
}

// ---------------------------------------------------------------------------
extern "C" void kernel_launch(void* const* d_in, const int* in_sizes, int n_in,
                              void* d_out, int out_size)
{
    const float* x    = (const float*)d_in[0];
    const float* Wih0 = (const float*)d_in[1];
    const float* Whh0 = (const float*)d_in[2];
    const float* bih0 = (const float*)d_in[3];
    const float* bhh0 = (const float*)d_in[4];
    const float* Wih1 = (const float*)d_in[5];
    const float* Whh1 = (const float*)d_in[6];
    const float* bih1 = (const float*)d_in[7];
    const float* bhh1 = (const float*)d_in[8];
    const float* Wih2 = (const float*)d_in[9];
    const float* Whh2 = (const float*)d_in[10];
    const float* bih2 = (const float*)d_in[11];
    const float* bhh2 = (const float*)d_in[12];
    const float* fc1w = (const float*)d_in[13];
    const float* fc1b = (const float*)d_in[14];
    const float* fc2w = (const float*)d_in[15];
    const float* fc2b = (const float*)d_in[16];
    float* y = (float*)d_out;
    (void)in_sizes; (void)n_in; (void)out_size;

    cudaFuncSetAttribute((const void*)gx_gemm<64>,
                         cudaFuncAttributeMaxDynamicSharedMemorySize, 65536);
    cudaFuncSetAttribute((const void*)gru_rec,
                         cudaFuncAttributeMaxDynamicSharedMemorySize, 57344);

    float* outp = nullptr;
    cudaGetSymbolAddress((void**)&outp, g_out);

    const dim3 gg(16, 512);
    const int rec_smem = 57344;

    // layer 0
    gx_gemm<16><<<gg, 256, (16 * G3 + 16 * 64) * 4>>>(x, (long)TT * IN_DIM, (long)IN_DIM, Wih0, bih0);
    gru_rec<<<128, 256, rec_smem>>>(Whh0, bhh0);
    // layer 1
    gx_gemm<64><<<gg, 256, 65536>>>(outp, 64L, (long)BB * HH, Wih1, bih1);
    gru_rec<<<128, 256, rec_smem>>>(Whh1, bhh1);
    // layer 2
    gx_gemm<64><<<gg, 256, 65536>>>(outp, 64L, (long)BB * HH, Wih2, bih2);
    gru_rec<<<128, 256, rec_smem>>>(Whh2, bhh2);
    // head
    head_kernel<<<4, 256>>>(fc1w, fc1b, fc2w, fc2b, y);
}